// round 11
// baseline (speedup 1.0000x reference)
#include <cuda_runtime.h>
#include <cuda_bf16.h>

#define TPB 1024
#define NWARP (TPB / 32)   // 32

// One row per CTA, one 4-element chunk per thread (1024*4 = 4096 = T).
// Lane stride 16B -> every LDG.128/STG.128 wavefront is 512B fully
// contiguous (R10's sector lesson). Single warp scan + warp-parallel
// cross-warp scan; __launch_bounds__(1024,2) -> <=32 regs, 2 CTAs/SM,
// 100% theoretical occupancy (R8 lesson: protect occupancy above all).
// idx_mask committed as int32 0/1 flags (verified R7 via rel_err + traffic).
__global__ __launch_bounds__(TPB, 2) void seg_mask_kernel(
    const float* __restrict__ x,
    const int*   __restrict__ idx_mask,       // [rows*T] int32 0/1
    const int*   __restrict__ mask_size,      // [S]
    const int*   __restrict__ mask_value,     // scalar
    float* __restrict__ out,                  // [rows*T]
    float* __restrict__ mask_out,             // [rows*T] or nullptr
    int S, int T)
{
    const int tid  = threadIdx.x;
    const int lane = tid & 31, wid = tid >> 5;
    const int row  = blockIdx.x;               // row = b*S + s
    const int s    = row % S;
    const long long base = (long long)row * T;
    const int t0   = tid * 4;

    // ---- front-batch loads, fully coalesced ----
    int4   ia = __ldcs((const int4*)(idx_mask + base + t0));
    float4 xa = __ldcs((const float4*)(x + base + t0));

    unsigned bits =
          ((unsigned)(ia.x != 0) << 0) | ((unsigned)(ia.y != 0) << 1)
        | ((unsigned)(ia.z != 0) << 2) | ((unsigned)(ia.w != 0) << 3);

    const int   m  = __ldg(mask_size + s);
    const float mv = (float)__ldg(mask_value);

    // ---- local "last start index" in this 4-chunk ----
    int v = bits ? (t0 + 31 - __clz(bits)) : -1;

    // ---- intra-warp inclusive max-scan ----
    #pragma unroll
    for (int off = 1; off < 32; off <<= 1) {
        int u = __shfl_up_sync(0xffffffffu, v, off);
        if (lane >= off) v = max(v, u);
    }
    __shared__ int wmax[NWARP];
    if (lane == 31) wmax[wid] = v;
    __syncthreads();

    // ---- cross-warp exclusive prefix, warp-parallel ----
    // Every warp scans the 32 warp-totals in its own lanes, then each
    // thread picks the inclusive value at (wid-1).
    int wv = wmax[lane];
    #pragma unroll
    for (int off = 1; off < 32; off <<= 1) {
        int u = __shfl_up_sync(0xffffffffu, wv, off);
        if (lane >= off) wv = max(wv, u);
    }
    int warp_excl = __shfl_sync(0xffffffffu, wv, (wid == 0) ? 0 : (wid - 1));
    if (wid == 0) warp_excl = -1;

    int incl_prev = __shfl_up_sync(0xffffffffu, v, 1);
    int excl = (lane == 0) ? warp_excl : max(warp_excl, incl_prev);

    // ---- compute out / mask ----
    float4 oa, ma;
    {
        const float* xp = (const float*)&xa;
        float* op = (float*)&oa; float* mp = (float*)&ma;
        int cur = excl;
        #pragma unroll
        for (int i = 0; i < 4; i++) {
            int t = t0 + i;
            if ((bits >> i) & 1u) cur = t;
            int lo = t - m; if (lo < 0) lo = 0;
            bool msk = (cur >= lo);             // cur == -1 always fails (lo >= 0)
            mp[i] = msk ? 1.0f : 0.0f;
            op[i] = msk ? mv : xp[i];
        }
    }

    // ---- grouped streaming stores ----
    __stcs((float4*)(out + base + t0), oa);
    if (mask_out)
        __stcs((float4*)(mask_out + base + t0), ma);
}

extern "C" void kernel_launch(void* const* d_in, const int* in_sizes, int n_in,
                              void* d_out, int out_size) {
    const float* x     = (const float*)d_in[0];
    const int*   idx   = (const int*)d_in[1];
    const int*   msize = (const int*)d_in[2];
    const int*   mval  = (const int*)d_in[3];
    float* out = (float*)d_out;

    const int T = 4096;
    const int N = in_sizes[0];          // B*S*T
    const int S = in_sizes[2];          // 128
    const int rows = N / T;             // B*S = 8192

    // Tuple output (out, mask) -> concatenated float32 if out_size covers both.
    float* mask_out = (out_size >= 2 * N) ? (out + (long long)N) : nullptr;

    seg_mask_kernel<<<rows, TPB>>>(x, idx, msize, mval, out, mask_out, S, T);
}

// round 12
// speedup vs baseline: 1.0910x; 1.0910x over previous
#include <cuda_runtime.h>
#include <cuda_bf16.h>

#define TPB 512
#define NWARP (TPB / 32)   // 16

// R10 layout (proven 77.9us / 78.4% DRAM): one row per CTA, two half-row
// 4-element chunks per thread, lane stride 16B -> 512B fully-contiguous
// wavefronts. Packed s16x2 scan handles both halves in one block scan.
// R12 change: __launch_bounds__(512,4) forces regs<=32 to recover the
// resident CTA lost at regs=36 (occ 62% -> ~82%). R11 lesson: keep 4
// loads/thread MLP and the 512-wide barrier; don't go to TPB=1024.
// idx_mask committed as int32 0/1 (verified R7 via rel_err + traffic).
__global__ __launch_bounds__(TPB, 4) void seg_mask_kernel(
    const float* __restrict__ x,
    const int*   __restrict__ idx_mask,       // [rows*T] int32 0/1
    const int*   __restrict__ mask_size,      // [S]
    const int*   __restrict__ mask_value,     // scalar
    float* __restrict__ out,                  // [rows*T]
    float* __restrict__ mask_out,             // [rows*T] or nullptr
    int S, int T)
{
    const int tid  = threadIdx.x;
    const int lane = tid & 31, wid = tid >> 5;
    const int row  = blockIdx.x;              // row = b*S + s
    const int s    = row % S;
    const long long base = (long long)row * T;
    const int half = T >> 1;                  // 2048
    const int t0a  = tid * 4;                 // first-half positions
    const int t0b  = half + tid * 4;          // second-half positions

    // ---- front-batch ALL loads, fully coalesced (lane stride 16B) ----
    int4   ia = __ldcs((const int4*)(idx_mask + base + t0a));
    int4   ib = __ldcs((const int4*)(idx_mask + base + t0b));
    float4 xa = __ldcs((const float4*)(x + base + t0a));
    float4 xb = __ldcs((const float4*)(x + base + t0b));

    unsigned bitsa =
          ((unsigned)(ia.x != 0) << 0) | ((unsigned)(ia.y != 0) << 1)
        | ((unsigned)(ia.z != 0) << 2) | ((unsigned)(ia.w != 0) << 3);
    unsigned bitsb =
          ((unsigned)(ib.x != 0) << 0) | ((unsigned)(ib.y != 0) << 1)
        | ((unsigned)(ib.z != 0) << 2) | ((unsigned)(ib.w != 0) << 3);

    const int   m  = __ldg(mask_size + s);
    const float mv = (float)__ldg(mask_value);

    // ---- local "last start index" per half, packed s16x2 (a=hi, b=lo) ----
    int la = bitsa ? (t0a + 31 - __clz(bitsa)) : -1;   // [-1, 2047]
    int lb = bitsb ? (t0b + 31 - __clz(bitsb)) : -1;   // [-1, 4095]
    unsigned p = ((unsigned)(la & 0xFFFF) << 16) | (unsigned)(lb & 0xFFFF);

    // ---- single packed block-wide max-scan ----
    #pragma unroll
    for (int off = 1; off < 32; off <<= 1) {
        unsigned u = __shfl_up_sync(0xffffffffu, p, off);
        if (lane >= off) p = __vmaxs2(p, u);
    }
    __shared__ unsigned wmax[NWARP];
    if (lane == 31) wmax[wid] = p;
    __syncthreads();
    unsigned incl_prev = __shfl_up_sync(0xffffffffu, p, 1);
    unsigned excl = (lane == 0) ? 0xFFFFFFFFu : incl_prev;  // (-1,-1)
    unsigned all  = 0xFFFFFFFFu;              // block-wide packed max
    #pragma unroll
    for (int w = 0; w < NWARP; w++) {
        unsigned wm = wmax[w];
        if (w < wid) excl = __vmaxs2(excl, wm);
        all = __vmaxs2(all, wm);
    }
    int excl_a = (int)((short)(excl >> 16));
    int tot_a  = (int)((short)(all  >> 16)); // first-half block total
    int excl_b = max((int)((short)(excl & 0xFFFF)), tot_a);

    // ---- compute out / mask for both halves ----
    float4 oa, ob, ma, mb;
    {
        const float* xp = (const float*)&xa;
        float* op = (float*)&oa; float* mp = (float*)&ma;
        int cur = excl_a;
        #pragma unroll
        for (int i = 0; i < 4; i++) {
            int t = t0a + i;
            if ((bitsa >> i) & 1u) cur = t;
            int lo = t - m; if (lo < 0) lo = 0;
            bool msk = (cur >= lo);
            mp[i] = msk ? 1.0f : 0.0f;
            op[i] = msk ? mv : xp[i];
        }
    }
    {
        const float* xp = (const float*)&xb;
        float* op = (float*)&ob; float* mp = (float*)&mb;
        int cur = excl_b;
        #pragma unroll
        for (int i = 0; i < 4; i++) {
            int t = t0b + i;
            if ((bitsb >> i) & 1u) cur = t;
            int lo = t - m; if (lo < 0) lo = 0;
            bool msk = (cur >= lo);
            mp[i] = msk ? 1.0f : 0.0f;
            op[i] = msk ? mv : xp[i];
        }
    }

    // ---- grouped, fully-coalesced streaming stores ----
    __stcs((float4*)(out + base + t0a), oa);
    __stcs((float4*)(out + base + t0b), ob);
    if (mask_out) {
        __stcs((float4*)(mask_out + base + t0a), ma);
        __stcs((float4*)(mask_out + base + t0b), mb);
    }
}

extern "C" void kernel_launch(void* const* d_in, const int* in_sizes, int n_in,
                              void* d_out, int out_size) {
    const float* x     = (const float*)d_in[0];
    const int*   idx   = (const int*)d_in[1];
    const int*   msize = (const int*)d_in[2];
    const int*   mval  = (const int*)d_in[3];
    float* out = (float*)d_out;

    const int T = 4096;
    const int N = in_sizes[0];          // B*S*T
    const int S = in_sizes[2];          // 128
    const int rows = N / T;             // B*S = 8192

    // Tuple output (out, mask) -> concatenated float32 if out_size covers both.
    float* mask_out = (out_size >= 2 * N) ? (out + (long long)N) : nullptr;

    seg_mask_kernel<<<rows, TPB>>>(x, idx, msize, mval, out, mask_out, S, T);
}

// round 13
// speedup vs baseline: 1.1055x; 1.0133x over previous
#include <cuda_runtime.h>
#include <cuda_bf16.h>

#define TPB 512
#define NWARP (TPB / 32)   // 16

// FINAL (lock-in of the R10 measured optimum: 77.9us kernel, 78.4% DRAM,
// 6.21 TB/s on a 536MB 50/50 R/W stream mix == the HBM turnaround ceiling).
// - One row per CTA; thread tid owns [4*tid,4*tid+4) of each half-row.
//   Lane stride 16B -> every LDG.128/STG.128 wavefront is 512B fully
//   contiguous (full 32B sectors; halves L1tex wavefronts vs blocked layout).
// - Both halves' last-start max-scans packed s16x2, ONE block scan (__vmaxs2);
//   second half's carry = max(its exclusive prefix, first half's block total).
// - .cs streaming hints on all 4 streams (write-back measured -3%).
// - Natural regs (36): forcing 32 (occ 62->85%) measured neutral-to-worse;
//   2-rows/thread (regs 48) -8%; TPB=1024 -9%; persistent grid neutral.
// - idx_mask committed as int32 0/1 (verified: rel_err==0 + HBM traffic
//   matches the int32 footprint, not the 1-byte-bool one).
__global__ __launch_bounds__(TPB) void seg_mask_kernel(
    const float* __restrict__ x,
    const int*   __restrict__ idx_mask,       // [rows*T] int32 0/1
    const int*   __restrict__ mask_size,      // [S]
    const int*   __restrict__ mask_value,     // scalar
    float* __restrict__ out,                  // [rows*T]
    float* __restrict__ mask_out,             // [rows*T] or nullptr
    int S, int T)
{
    const int tid  = threadIdx.x;
    const int lane = tid & 31, wid = tid >> 5;
    const int row  = blockIdx.x;              // row = b*S + s
    const int s    = row % S;
    const long long base = (long long)row * T;
    const int half = T >> 1;                  // 2048
    const int t0a  = tid * 4;                 // first-half positions
    const int t0b  = half + tid * 4;          // second-half positions

    // ---- front-batch ALL loads, fully coalesced (lane stride 16B) ----
    const int4*   ipa = (const int4*)(idx_mask + base + t0a);
    const int4*   ipb = (const int4*)(idx_mask + base + t0b);
    const float4* xva = (const float4*)(x + base + t0a);
    const float4* xvb = (const float4*)(x + base + t0b);
    int4   ia = __ldcs(ipa);
    int4   ib = __ldcs(ipb);
    float4 xa = __ldcs(xva);
    float4 xb = __ldcs(xvb);

    unsigned bitsa =
          ((unsigned)(ia.x != 0) << 0) | ((unsigned)(ia.y != 0) << 1)
        | ((unsigned)(ia.z != 0) << 2) | ((unsigned)(ia.w != 0) << 3);
    unsigned bitsb =
          ((unsigned)(ib.x != 0) << 0) | ((unsigned)(ib.y != 0) << 1)
        | ((unsigned)(ib.z != 0) << 2) | ((unsigned)(ib.w != 0) << 3);

    const int   m  = __ldg(mask_size + s);
    const float mv = (float)__ldg(mask_value);

    // ---- local "last start index" per half, packed s16x2 (a=hi, b=lo) ----
    int la = bitsa ? (t0a + 31 - __clz(bitsa)) : -1;   // [-1, 2047]
    int lb = bitsb ? (t0b + 31 - __clz(bitsb)) : -1;   // [-1, 4095]
    unsigned p = ((unsigned)(la & 0xFFFF) << 16) | (unsigned)(lb & 0xFFFF);

    // ---- single packed block-wide max-scan ----
    #pragma unroll
    for (int off = 1; off < 32; off <<= 1) {
        unsigned u = __shfl_up_sync(0xffffffffu, p, off);
        if (lane >= off) p = __vmaxs2(p, u);
    }
    __shared__ unsigned wmax[NWARP];
    if (lane == 31) wmax[wid] = p;
    __syncthreads();
    unsigned incl_prev = __shfl_up_sync(0xffffffffu, p, 1);
    unsigned excl = (lane == 0) ? 0xFFFFFFFFu : incl_prev;  // (-1,-1)
    int tot_a = -1;                           // block-wide max of first half
    #pragma unroll
    for (int w = 0; w < NWARP; w++) {
        unsigned wm = wmax[w];
        if (w < wid) excl = __vmaxs2(excl, wm);
        tot_a = max(tot_a, (int)((short)(wm >> 16)));
    }
    int excl_a = (int)((short)(excl >> 16));
    int excl_b = max((int)((short)(excl & 0xFFFF)), tot_a);

    // ---- compute out / mask for both halves ----
    float4 oa, ob, ma, mb;
    {
        const float* xp = (const float*)&xa;
        float* op = (float*)&oa; float* mp = (float*)&ma;
        int cur = excl_a;
        #pragma unroll
        for (int i = 0; i < 4; i++) {
            int t = t0a + i;
            if ((bitsa >> i) & 1u) cur = t;
            int lo = t - m; if (lo < 0) lo = 0;
            bool msk = (cur >= lo);
            mp[i] = msk ? 1.0f : 0.0f;
            op[i] = msk ? mv : xp[i];
        }
    }
    {
        const float* xp = (const float*)&xb;
        float* op = (float*)&ob; float* mp = (float*)&mb;
        int cur = excl_b;
        #pragma unroll
        for (int i = 0; i < 4; i++) {
            int t = t0b + i;
            if ((bitsb >> i) & 1u) cur = t;
            int lo = t - m; if (lo < 0) lo = 0;
            bool msk = (cur >= lo);
            mp[i] = msk ? 1.0f : 0.0f;
            op[i] = msk ? mv : xp[i];
        }
    }

    // ---- grouped, fully-coalesced streaming stores ----
    __stcs((float4*)(out + base + t0a), oa);
    __stcs((float4*)(out + base + t0b), ob);
    if (mask_out) {
        __stcs((float4*)(mask_out + base + t0a), ma);
        __stcs((float4*)(mask_out + base + t0b), mb);
    }
}

extern "C" void kernel_launch(void* const* d_in, const int* in_sizes, int n_in,
                              void* d_out, int out_size) {
    const float* x     = (const float*)d_in[0];
    const int*   idx   = (const int*)d_in[1];
    const int*   msize = (const int*)d_in[2];
    const int*   mval  = (const int*)d_in[3];
    float* out = (float*)d_out;

    const int T = 4096;
    const int N = in_sizes[0];          // B*S*T
    const int S = in_sizes[2];          // 128
    const int rows = N / T;             // B*S = 8192

    // Tuple output (out, mask) -> concatenated float32 if out_size covers both.
    float* mask_out = (out_size >= 2 * N) ? (out + (long long)N) : nullptr;

    seg_mask_kernel<<<rows, TPB>>>(x, idx, msize, mval, out, mask_out, S, T);
}